// round 16
// baseline (speedup 1.0000x reference)
#include <cuda_runtime.h>
#include <math.h>
#include <stdint.h>

// Problem constants
#define Bb   4
#define Tt   2048
#define Ee   512
#define Dd   512
#define Nn   16
#define Ll   4
#define TC   32              // chunk length (time steps per thread)
#define NCH  (Tt / TC)       // 64 chunks
#define DN   (Dd * Nn)       // 8192
#define DBLK 2               // d-channels per block in fused scan
#define SXS  34              // padded smem row stride (floats, even for ull)

typedef unsigned long long ull;

__device__ __forceinline__ ull pack2(float lo, float hi) {
    ull r; asm("mov.b64 %0, {%1,%2};" : "=l"(r) : "f"(lo), "f"(hi)); return r;
}
__device__ __forceinline__ void unpack2(ull v, float& lo, float& hi) {
    asm("mov.b64 {%0,%1}, %2;" : "=f"(lo), "=f"(hi) : "l"(v));
}
__device__ __forceinline__ ull fma2(ull a, ull b, ull c) {
    ull d; asm("fma.rn.f32x2 %0, %1, %2, %3;" : "=l"(d) : "l"(a), "l"(b), "l"(c));
    return d;
}
__device__ __forceinline__ uint32_t f2tf(float f) {
    uint32_t u; asm("cvt.rna.tf32.f32 %0, %1;" : "=r"(u) : "f"(f)); return u;
}
__device__ __forceinline__ void ldsm4(uint32_t& r0, uint32_t& r1, uint32_t& r2,
                                      uint32_t& r3, const uint32_t* p) {
    uint32_t a = (uint32_t)__cvta_generic_to_shared(p);
    asm volatile("ldmatrix.sync.aligned.m8n8.x4.shared.b16 {%0,%1,%2,%3}, [%4];"
                 : "=r"(r0), "=r"(r1), "=r"(r2), "=r"(r3) : "r"(a));
}
__device__ __forceinline__ void mma_tf32(float* c, const uint32_t* a,
                                         uint32_t b0, uint32_t b1) {
    asm volatile("mma.sync.aligned.m16n8k8.row.col.f32.tf32.tf32.f32 "
                 "{%0,%1,%2,%3}, {%4,%5,%6,%7}, {%8,%9}, {%0,%1,%2,%3};"
                 : "+f"(c[0]), "+f"(c[1]), "+f"(c[2]), "+f"(c[3])
                 : "r"(a[0]), "r"(a[1]), "r"(a[2]), "r"(a[3]), "r"(b0), "r"(b1));
}
__device__ __forceinline__ void cp_async16(uint32_t dst_smem, const void* src) {
    asm volatile("cp.async.cg.shared.global [%0], [%1], 16;"
                 :: "r"(dst_smem), "l"(src));
}
__device__ __forceinline__ void cp_commit() {
    asm volatile("cp.async.commit_group;");
}
__device__ __forceinline__ void cp_wait0() {
    asm volatile("cp.async.wait_group 0;");
}

// Scratch (static device globals; no runtime allocation)
__device__ float g_ht[(size_t)Bb * Dd * Tt];       // residual stream, TRANSPOSED [b][d][t]
__device__ uint32_t g_Xt[(size_t)Bb * Tt * Ee];    // X pre-converted to tf32 (row-major)
__device__ uint32_t g_Wt[(size_t)Dd * Ee];         // W transposed, tf32 [d][e]
__device__ float g_bf[(size_t)Dd * Tt];            // bias[d] + freq[t][d], [d][t]
__device__ float g_Abar [Ll * DN];
__device__ float g_CB   [Ll * DN];                 // C * Bbar
__device__ float g_AbarP[Ll * DN];                 // Abar^TC
__device__ float g_swf0[Dd], g_swen[Dd];           // scale*weight per head
__device__ float g_hc[4];                          // SWf0, BWf0, SWen, BWen
__device__ float g_hp[16 * Bb * Tt];               // head partials [dpart(4)][sum(4)][B*T]

// ---------------------------------------------------------------------------
// Mega-prep: ONE launch, partitioned by blockIdx.
// ---------------------------------------------------------------------------
#define XBLKS   ((Bb * Tt * Ee) / 1024)       // 4096
#define BFBLKS  ((Dd / 32) * (Tt / 32))       // 1024
#define WTBLKS  ((Dd / 32) * (Ee / 32))       // 256
#define SSMBLKS ((Ll * DN) / 256)             // 128
#define MPREP_BLOCKS (XBLKS + BFBLKS + WTBLKS + SSMBLKS + 1)   // 5505

__global__ __launch_bounds__(256)
void mega_prep_kernel(const float* __restrict__ X, const float* __restrict__ W,
                      const float* __restrict__ bias, const float* __restrict__ freq,
                      const float* __restrict__ A_log, const float* __restrict__ B_ssm,
                      const float* __restrict__ C_ssm, const float* __restrict__ log_dt,
                      const float* __restrict__ s_f0, const float* __restrict__ bi_f0,
                      const float* __restrict__ w_f0,
                      const float* __restrict__ s_en, const float* __restrict__ bi_en,
                      const float* __restrict__ w_en) {
    __shared__ float sh[32][33];
    int bi = blockIdx.x;
    int tid = threadIdx.x;

    if (bi < XBLKS) {
        size_t base = (size_t)bi * 1024 + tid * 4;
        float4 v = *(const float4*)(X + base);
        *(uint4*)(g_Xt + base) = make_uint4(f2tf(v.x), f2tf(v.y), f2tf(v.z), f2tf(v.w));
    } else if (bi < XBLKS + BFBLKS) {
        int t2 = bi - XBLKS;
        int d0 = (t2 & 15) * 32, t0 = (t2 >> 4) * 32;
        int tx = tid & 31, ty = tid >> 5;       // (32, 8)
#pragma unroll
        for (int j = 0; j < 4; j++)
            sh[ty + j * 8][tx] = freq[(size_t)(t0 + ty + j * 8) * Dd + d0 + tx];
        __syncthreads();
#pragma unroll
        for (int j = 0; j < 4; j++)
            g_bf[(size_t)(d0 + ty + j * 8) * Tt + t0 + tx] =
                sh[tx][ty + j * 8] + bias[d0 + ty + j * 8];
    } else if (bi < XBLKS + BFBLKS + WTBLKS) {
        int t2 = bi - (XBLKS + BFBLKS);
        int d0 = (t2 & 15) * 32, e0 = (t2 >> 4) * 32;
        int tx = tid & 31, ty = tid >> 5;
#pragma unroll
        for (int j = 0; j < 4; j++)
            sh[ty + j * 8][tx] = W[(size_t)(e0 + ty + j * 8) * Dd + d0 + tx];
        __syncthreads();
#pragma unroll
        for (int j = 0; j < 4; j++)
            g_Wt[(size_t)(d0 + ty + j * 8) * Ee + e0 + tx] = f2tf(sh[tx][ty + j * 8]);
    } else if (bi < XBLKS + BFBLKS + WTBLKS + SSMBLKS) {
        int idx = (bi - (XBLKS + BFBLKS + WTBLKS)) * 256 + tid;
        int l  = idx / DN;
        int dn = idx % DN;
        int d  = dn / Nn;
        float dt = expf(log_dt[l * Dd + d]);
        float A  = -expf(A_log[idx]);
        float dA = dt * A;
        float ab = expf(dA);
        g_Abar [idx] = ab;
        g_CB   [idx] = (ab - 1.0f) / A * B_ssm[idx] * C_ssm[idx];
        g_AbarP[idx] = expf(dA * (float)TC);
    } else {
        float* shf = &sh[0][0];
        float sum[4] = {0.0f, 0.0f, 0.0f, 0.0f};
#pragma unroll
        for (int k = 0; k < 2; k++) {
            int d = tid + k * 256;
            float wf = w_f0[d], we = w_en[d];
            float v0 = s_f0[d] * wf;
            float v1 = bi_f0[d] * wf;
            float v2 = s_en[d] * we;
            float v3 = bi_en[d] * we;
            g_swf0[d] = v0; g_swen[d] = v2;
            sum[0] += v0; sum[1] += v1; sum[2] += v2; sum[3] += v3;
        }
        int lane = tid & 31, w = tid >> 5;
#pragma unroll
        for (int j = 0; j < 4; j++) {
            float x = sum[j];
#pragma unroll
            for (int o = 16; o > 0; o >>= 1) x += __shfl_xor_sync(0xffffffffu, x, o);
            if (lane == 0) shf[j * 8 + w] = x;
        }
        __syncthreads();
        if (tid < 4) {
            float s = 0.0f;
#pragma unroll
            for (int k = 0; k < 8; k++) s += shf[tid * 8 + k];
            g_hc[tid] = s;
        }
    }
}

// ---------------------------------------------------------------------------
// TF32 GEMM, 128x128x16 tiles (R13 state). All smem fills via cp.async.
// ---------------------------------------------------------------------------
#define AST 20     // smem row stride (words)
#define BUFW 2560  // words per buffer (128 rows * 20)

__global__ __launch_bounds__(256, 2)
void gemm_tf32_kernel() {
    __shared__ __align__(16) uint32_t smem[4 * BUFW];
    uint32_t* As = smem;
    uint32_t* Bs = smem + 2 * BUFW;

    int tid = threadIdx.x;
    int lane = tid & 31, wid = tid >> 5;
    int warp_m = wid >> 2, warp_n = wid & 3;
    int rowBase = blockIdx.y * 128;
    int colBase = blockIdx.x * 128;

    float acc[4][4][4];
#pragma unroll
    for (int i = 0; i < 4; i++)
#pragma unroll
        for (int j = 0; j < 4; j++)
#pragma unroll
            for (int k = 0; k < 4; k++) acc[i][j][k] = 0.0f;

    int a_row = (lane & 7) + ((lane >> 3) & 1) * 8;
    int a_colw = (lane >> 4) * 4;
    const uint32_t* aPtr = As + (warp_m * 64 + a_row) * AST + a_colw;
    int b_row = (lane & 7) + ((lane >> 4) << 3);
    int b_colw = ((lane >> 3) & 1) * 4;
    const uint32_t* bPtr = Bs + (warp_n * 32 + b_row) * AST + b_colw;

    int frow = tid >> 2;
    int fcol = (tid & 3) << 2;

    const uint32_t* Xp = g_Xt + (size_t)rowBase * Ee;
    const uint32_t* Wp = g_Wt + (size_t)colBase * Ee;

    uint32_t as0 = (uint32_t)__cvta_generic_to_shared(&As[frow * AST + fcol]);
    uint32_t as1 = (uint32_t)__cvta_generic_to_shared(&As[(frow + 64) * AST + fcol]);
    uint32_t bs0 = (uint32_t)__cvta_generic_to_shared(&Bs[frow * AST + fcol]);
    uint32_t bs1 = (uint32_t)__cvta_generic_to_shared(&Bs[(frow + 64) * AST + fcol]);

    cp_async16(as0, Xp + (size_t)frow * Ee + fcol);
    cp_async16(as1, Xp + (size_t)(frow + 64) * Ee + fcol);
    cp_async16(bs0, Wp + (size_t)frow * Ee + fcol);
    cp_async16(bs1, Wp + (size_t)(frow + 64) * Ee + fcol);
    cp_commit();
    cp_wait0();
    __syncthreads();

    int buf = 0;
    for (int kt = 16; kt < Ee; kt += 16) {
        int nb = buf ^ 1;
        uint32_t off = nb * (BUFW * 4);
        cp_async16(as0 + off, Xp + (size_t)frow * Ee + kt + fcol);
        cp_async16(as1 + off, Xp + (size_t)(frow + 64) * Ee + kt + fcol);
        cp_async16(bs0 + off, Wp + (size_t)frow * Ee + kt + fcol);
        cp_async16(bs1 + off, Wp + (size_t)(frow + 64) * Ee + kt + fcol);
        cp_commit();

        const uint32_t* aB = aPtr + buf * BUFW;
        const uint32_t* bB = bPtr + buf * BUFW;
        uint32_t a[2][4][4], bb[2][2][4];
#pragma unroll
        for (int k8 = 0; k8 < 2; k8++) {
#pragma unroll
            for (int mi = 0; mi < 4; mi++)
                ldsm4(a[k8][mi][0], a[k8][mi][1], a[k8][mi][2], a[k8][mi][3],
                      aB + mi * (16 * AST) + k8 * 8);
#pragma unroll
            for (int nj = 0; nj < 2; nj++)
                ldsm4(bb[k8][nj][0], bb[k8][nj][1], bb[k8][nj][2], bb[k8][nj][3],
                      bB + nj * (16 * AST) + k8 * 8);
        }
#pragma unroll
        for (int k8 = 0; k8 < 2; k8++)
#pragma unroll
            for (int mi = 0; mi < 4; mi++)
#pragma unroll
                for (int nj = 0; nj < 2; nj++) {
                    mma_tf32(acc[mi][2 * nj + 0], a[k8][mi], bb[k8][nj][0], bb[k8][nj][1]);
                    mma_tf32(acc[mi][2 * nj + 1], a[k8][mi], bb[k8][nj][2], bb[k8][nj][3]);
                }

        cp_wait0();
        __syncthreads();
        buf = nb;
    }

    {
        const uint32_t* aB = aPtr + buf * BUFW;
        const uint32_t* bB = bPtr + buf * BUFW;
        uint32_t a[2][4][4], bb[2][2][4];
#pragma unroll
        for (int k8 = 0; k8 < 2; k8++) {
#pragma unroll
            for (int mi = 0; mi < 4; mi++)
                ldsm4(a[k8][mi][0], a[k8][mi][1], a[k8][mi][2], a[k8][mi][3],
                      aB + mi * (16 * AST) + k8 * 8);
#pragma unroll
            for (int nj = 0; nj < 2; nj++)
                ldsm4(bb[k8][nj][0], bb[k8][nj][1], bb[k8][nj][2], bb[k8][nj][3],
                      bB + nj * (16 * AST) + k8 * 8);
        }
#pragma unroll
        for (int k8 = 0; k8 < 2; k8++)
#pragma unroll
            for (int mi = 0; mi < 4; mi++)
#pragma unroll
                for (int nj = 0; nj < 2; nj++) {
                    mma_tf32(acc[mi][2 * nj + 0], a[k8][mi], bb[k8][nj][0], bb[k8][nj][1]);
                    mma_tf32(acc[mi][2 * nj + 1], a[k8][mi], bb[k8][nj][2], bb[k8][nj][3]);
                }
    }
    __syncthreads();

    float* SE = (float*)smem;            // [64][132] floats
    int g = lane >> 2, tk = lane & 3;
    int b = rowBase >> 11;
    int t0 = rowBase & (Tt - 1);

#pragma unroll
    for (int p = 0; p < 2; p++) {
        if ((warp_n >> 1) == p) {
#pragma unroll
            for (int mi = 0; mi < 4; mi++) {
#pragma unroll
                for (int ni = 0; ni < 4; ni++) {
                    int rl = warp_m * 64 + mi * 16 + g;
                    int cl = warp_n * 32 + ni * 8 + 2 * tk;
                    int cls = cl - p * 64;
                    SE[cls * 132 + rl]           = acc[mi][ni][0];
                    SE[(cls + 1) * 132 + rl]     = acc[mi][ni][1];
                    SE[cls * 132 + rl + 8]       = acc[mi][ni][2];
                    SE[(cls + 1) * 132 + rl + 8] = acc[mi][ni][3];
                }
            }
        }
        __syncthreads();
#pragma unroll
        for (int i = 0; i < 8; i++) {
            int idx = i * 256 + tid;
            int dr = idx >> 5;
            int w  = idx & 31;
            int dg = colBase + p * 64 + dr;
            float4 v = *(float4*)&SE[dr * 132 + w * 4];
            float4 bf = *(const float4*)&g_bf[(size_t)dg * Tt + t0 + w * 4];
            v.x += bf.x; v.y += bf.y; v.z += bf.z; v.w += bf.w;
            *(float4*)&g_ht[((size_t)(b * Dd) + dg) * Tt + t0 + w * 4] = v;
        }
        __syncthreads();
    }
}

// ---------------------------------------------------------------------------
// Fused 4-layer S4 stack (R8 state — best measured, 59.6us). Block = 128 thr.
// ---------------------------------------------------------------------------
__global__ __launch_bounds__(128, 7)
void s4_stack_kernel(const float* __restrict__ D_skip) {
    __shared__ float sx[NCH * SXS];     // 8.7 KB
    __shared__ float us[DBLK * Tt];     // 16 KB

    int tid  = threadIdx.x;
    int dl   = tid & 1;
    int c    = tid >> 1;
    int b    = blockIdx.x >> 8;
    int dblk = blockIdx.x & 255;
    int d    = dblk * DBLK + dl;
    int rot  = tid & 31;
    int chanbase = dl * Tt + c * TC;

    int seg = tid & 3;
    int dn  = tid >> 2;
    int dl2 = dn >> 4, n2 = dn & 15;

    const float4* gb4 = (const float4*)(g_ht + ((size_t)(b * Dd) + dblk * DBLK) * Tt);
#pragma unroll
    for (int j = 0; j < 8; j++) {
        int p = j * 128 + tid;
        float4 v = gb4[p];
        int ch = p >> 9;
        int t  = (p & 511) << 2;
        int base = ch * Tt + (t & ~31);
        int rr = (((t >> 5) << 1) + ch) & 31;
        int i0 = t & 31;
        us[base + ((i0 + 0) ^ rr)] = v.x;
        us[base + ((i0 + 1) ^ rr)] = v.y;
        us[base + ((i0 + 2) ^ rr)] = v.z;
        us[base + ((i0 + 3) ^ rr)] = v.w;
    }
    __syncthreads();

#pragma unroll 1
    for (int l = 0; l < Ll; l++) {
        ull a2[8];
        {
            const float4* ap4 = (const float4*)(g_Abar + (size_t)l * DN + d * Nn);
#pragma unroll
            for (int q = 0; q < 4; q++) {
                float4 v = ap4[q];
                a2[2*q]   = pack2(v.x, v.y);
                a2[2*q+1] = pack2(v.z, v.w);
            }
        }

        ull z2[8];
#pragma unroll
        for (int q = 0; q < 8; q++) z2[q] = 0ull;
#pragma unroll
        for (int i = 0; i < TC; i++) {
            float uu = us[chanbase + (i ^ rot)];
            ull u2 = pack2(uu, uu);
#pragma unroll
            for (int q = 0; q < 8; q++)
                z2[q] = fma2(a2[q], z2[q], u2);
        }
        {
            ull* so = (ull*)(sx + c * SXS + dl * Nn);
#pragma unroll
            for (int q = 0; q < 8; q++) so[q] = z2[q];
        }
        __syncthreads();

        {
            float ap = g_AbarP[(size_t)l * DN + (dblk * DBLK + dl2) * Nn + n2];

            float F = 0.0f;
#pragma unroll
            for (int j = 0; j < 16; j++)
                F = fmaf(ap, F, sx[(seg * 16 + j) * SXS + dn]);

            float p2 = ap * ap, p4 = p2 * p2, p8 = p4 * p4;
            float m  = p8 * p8;

            float Fp = __shfl_up_sync(0xffffffffu, F, 1, 4);
            float mp = __shfl_up_sync(0xffffffffu, m, 1, 4);
            if (seg >= 1) { F = fmaf(m, Fp, F); m *= mp; }
            Fp = __shfl_up_sync(0xffffffffu, F, 2, 4);
            mp = __shfl_up_sync(0xffffffffu, m, 2, 4);
            if (seg >= 2) { F = fmaf(m, Fp, F); m *= mp; }

            float carry = __shfl_up_sync(0xffffffffu, F, 1, 4);
            if (seg == 0) carry = 0.0f;

            float xs = carry;
            float fcur = sx[(seg * 16) * SXS + dn];
#pragma unroll
            for (int j = 0; j < 16; j++) {
                float fnext = (j < 15) ? sx[(seg * 16 + j + 1) * SXS + dn] : 0.0f;
                sx[(seg * 16 + j) * SXS + dn] = xs;
                xs = fmaf(ap, xs, fcur);
                fcur = fnext;
            }
        }
        __syncthreads();

        ull cb2[8];
        {
            const float4* cp4 = (const float4*)(g_CB + (size_t)l * DN + d * Nn);
#pragma unroll
            for (int q = 0; q < 4; q++) {
                float4 v = cp4[q];
                cb2[2*q]   = pack2(v.x, v.y);
                cb2[2*q+1] = pack2(v.z, v.w);
            }
        }
        float dsk = D_skip[l * Dd + d];

        {
            const ull* si = (const ull*)(sx + c * SXS + dl * Nn);
#pragma unroll
            for (int q = 0; q < 8; q++) z2[q] = si[q];
        }

#pragma unroll
        for (int i = 0; i < TC; i++) {
            float uu = us[chanbase + (i ^ rot)];
            ull u2 = pack2(uu, uu);
            ull y2 = 0ull;
#pragma unroll
            for (int q = 0; q < 8; q++) {
                z2[q] = fma2(a2[q], z2[q], u2);
                y2 = fma2(z2[q], cb2[q], y2);
            }
            float ylo, yhi; unpack2(y2, ylo, yhi);
            float y = ylo + yhi;
            y = fmaf(dsk, uu, y);
            float yy = y * y;
            float inner2 = 1.5957691216057308f * (y + 0.044715f * y * yy);
            float e = __expf(-inner2);
            float g = __fdividef(y, 1.0f + e);
            us[chanbase + (i ^ rot)] = uu + g;
        }
    }
    __syncthreads();

    float4* gb4o = (float4*)(g_ht + ((size_t)(b * Dd) + dblk * DBLK) * Tt);
#pragma unroll
    for (int j = 0; j < 8; j++) {
        int p = j * 128 + tid;
        int ch = p >> 9;
        int t  = (p & 511) << 2;
        int base = ch * Tt + (t & ~31);
        int rr = (((t >> 5) << 1) + ch) & 31;
        int i0 = t & 31;
        float4 v;
        v.x = us[base + ((i0 + 0) ^ rr)];
        v.y = us[base + ((i0 + 1) ^ rr)];
        v.z = us[base + ((i0 + 2) ^ rr)];
        v.w = us[base + ((i0 + 3) ^ rr)];
        gb4o[p] = v;
    }
}

// ---------------------------------------------------------------------------
// Head main: partial sums over 128 d per block. Grid = 4 dparts x 256 trows.
// Block 512 thr: g = tid>>3 (64 groups x 2 d), lt = tid&7 (4 t each).
// Warp folds 4 g-groups via shfl; 16 warps reduced in smem; partials -> g_hp.
// ---------------------------------------------------------------------------
__global__ __launch_bounds__(512)
void head_main_kernel() {
    __shared__ float sh[16][4][32];
    int tid = threadIdx.x;
    int lane = tid & 31, w = tid >> 5;
    int g = tid >> 3;
    int lt = tid & 7;
    int dpart = blockIdx.x >> 8;            // 0..3
    int trow  = blockIdx.x & 255;
    int rowBase = trow * 32;
    int b = rowBase >> 11, t0 = rowBase & (Tt - 1);
    int dbase = dpart * 128 + g * 2;

    const float* hp = g_ht + ((size_t)(b * Dd) + dbase) * Tt + t0 + lt * 4;

    float acc[4][4];
#pragma unroll
    for (int j = 0; j < 4; j++)
#pragma unroll
        for (int k = 0; k < 4; k++) acc[j][k] = 0.0f;

#pragma unroll
    for (int dd = 0; dd < 2; dd++) {
        float4 v = *(const float4*)(hp + (size_t)dd * Tt);
        float wf = __ldg(g_swf0 + dbase + dd), we = __ldg(g_swen + dbase + dd);
        acc[0][0] += v.x; acc[0][1] += v.y; acc[0][2] += v.z; acc[0][3] += v.w;
        acc[1][0] = fmaf(v.x, v.x, acc[1][0]);
        acc[1][1] = fmaf(v.y, v.y, acc[1][1]);
        acc[1][2] = fmaf(v.z, v.z, acc[1][2]);
        acc[1][3] = fmaf(v.w, v.w, acc[1][3]);
        acc[2][0] = fmaf(v.x, wf, acc[2][0]);
        acc[2][1] = fmaf(v.y, wf, acc[2][1]);
        acc[2][2] = fmaf(v.z, wf, acc[2][2]);
        acc[2][3] = fmaf(v.w, wf, acc[2][3]);
        acc[3][0] = fmaf(v.x, we, acc[3][0]);
        acc[3][1] = fmaf(v.y, we, acc[3][1]);
        acc[3][2] = fmaf(v.z, we, acc[3][2]);
        acc[3][3] = fmaf(v.w, we, acc[3][3]);
    }

    // Fold the warp's 4 g-groups (lanes with same lane&7 share the t set)
#pragma unroll
    for (int j = 0; j < 4; j++)
#pragma unroll
        for (int k = 0; k < 4; k++) {
            acc[j][k] += __shfl_xor_sync(0xffffffffu, acc[j][k], 8);
            acc[j][k] += __shfl_xor_sync(0xffffffffu, acc[j][k], 16);
        }

    if (lane < 8) {
#pragma unroll
        for (int j = 0; j < 4; j++)
#pragma unroll
            for (int k = 0; k < 4; k++)
                sh[w][j][lane * 4 + k] = acc[j][k];
    }
    __syncthreads();

    if (tid < 32) {
        int tt = tid;
        float a[4] = {0.0f, 0.0f, 0.0f, 0.0f};
#pragma unroll
        for (int o = 0; o < 16; o++) {
            a[0] += sh[o][0][tt]; a[1] += sh[o][1][tt];
            a[2] += sh[o][2][tt]; a[3] += sh[o][3][tt];
        }
#pragma unroll
        for (int j = 0; j < 4; j++)
            g_hp[(dpart * 4 + j) * (Bb * Tt) + rowBase + tt] = a[j];
    }
}

// ---------------------------------------------------------------------------
// Head finalize: combine 4 d-part partials, LN + projections, write out.
// ---------------------------------------------------------------------------
__global__ __launch_bounds__(256)
void head_fin_kernel(const float* __restrict__ b_f0, const float* __restrict__ b_en,
                     float* __restrict__ out) {
    int t = blockIdx.x * 256 + threadIdx.x;      // 0 .. B*T-1
    float a0 = 0.0f, a1 = 0.0f, a2 = 0.0f, a3 = 0.0f;
#pragma unroll
    for (int p = 0; p < 4; p++) {
        a0 += g_hp[(p * 4 + 0) * (Bb * Tt) + t];
        a1 += g_hp[(p * 4 + 1) * (Bb * Tt) + t];
        a2 += g_hp[(p * 4 + 2) * (Bb * Tt) + t];
        a3 += g_hp[(p * 4 + 3) * (Bb * Tt) + t];
    }
    float mu = a0 * (1.0f / Dd);
    float var = a1 * (1.0f / Dd) - mu * mu;
    float rstd = rsqrtf(var + 1e-5f);
    out[t]                 = rstd * (a2 - mu * g_hc[0]) + g_hc[1] + b_f0[0];
    out[(size_t)Bb * Tt + t] = rstd * (a3 - mu * g_hc[2]) + g_hc[3] + b_en[0];
}

// ---------------------------------------------------------------------------
extern "C" void kernel_launch(void* const* d_in, const int* in_sizes, int n_in,
                              void* d_out, int out_size) {
    const float* text_emb = (const float*)d_in[0];
    const float* W_in     = (const float*)d_in[1];
    const float* b_in     = (const float*)d_in[2];
    const float* freq_pe  = (const float*)d_in[3];
    const float* A_log    = (const float*)d_in[4];
    const float* B_ssm    = (const float*)d_in[5];
    const float* C_ssm    = (const float*)d_in[6];
    const float* log_dt   = (const float*)d_in[7];
    const float* D_skip   = (const float*)d_in[8];
    const float* ln_f0_s  = (const float*)d_in[9];
    const float* ln_f0_b  = (const float*)d_in[10];
    const float* W_f0     = (const float*)d_in[11];
    const float* b_f0     = (const float*)d_in[12];
    const float* ln_en_s  = (const float*)d_in[13];
    const float* ln_en_b  = (const float*)d_in[14];
    const float* W_en     = (const float*)d_in[15];
    const float* b_en     = (const float*)d_in[16];
    float* out = (float*)d_out;

    mega_prep_kernel<<<MPREP_BLOCKS, 256>>>(
        text_emb, W_in, b_in, freq_pe,
        A_log, B_ssm, C_ssm, log_dt,
        ln_f0_s, ln_f0_b, W_f0, ln_en_s, ln_en_b, W_en);

    dim3 ggrid(Dd / 128, (Bb * Tt) / 128);
    gemm_tf32_kernel<<<ggrid, 256>>>();

    s4_stack_kernel<<<Bb * (Dd / DBLK), 128>>>(D_skip);

    head_main_kernel<<<4 * (Bb * Tt) / 32, 512>>>();
    head_fin_kernel<<<(Bb * Tt) / 256, 256>>>(b_f0, b_en, out);
}

// round 17
// speedup vs baseline: 1.0845x; 1.0845x over previous
#include <cuda_runtime.h>
#include <math.h>
#include <stdint.h>

// Problem constants
#define Bb   4
#define Tt   2048
#define Ee   512
#define Dd   512
#define Nn   16
#define Ll   4
#define TC   32              // chunk length (time steps per thread)
#define NCH  (Tt / TC)       // 64 chunks
#define DN   (Dd * Nn)       // 8192
#define DBLK 2               // d-channels per block in fused scan
#define SXS  34              // padded smem row stride (floats, even for ull)

typedef unsigned long long ull;

__device__ __forceinline__ ull pack2(float lo, float hi) {
    ull r; asm("mov.b64 %0, {%1,%2};" : "=l"(r) : "f"(lo), "f"(hi)); return r;
}
__device__ __forceinline__ void unpack2(ull v, float& lo, float& hi) {
    asm("mov.b64 {%0,%1}, %2;" : "=f"(lo), "=f"(hi) : "l"(v));
}
__device__ __forceinline__ ull fma2(ull a, ull b, ull c) {
    ull d; asm("fma.rn.f32x2 %0, %1, %2, %3;" : "=l"(d) : "l"(a), "l"(b), "l"(c));
    return d;
}
__device__ __forceinline__ uint32_t f2tf(float f) {
    uint32_t u; asm("cvt.rna.tf32.f32 %0, %1;" : "=r"(u) : "f"(f)); return u;
}
__device__ __forceinline__ void ldsm4(uint32_t& r0, uint32_t& r1, uint32_t& r2,
                                      uint32_t& r3, const uint32_t* p) {
    uint32_t a = (uint32_t)__cvta_generic_to_shared(p);
    asm volatile("ldmatrix.sync.aligned.m8n8.x4.shared.b16 {%0,%1,%2,%3}, [%4];"
                 : "=r"(r0), "=r"(r1), "=r"(r2), "=r"(r3) : "r"(a));
}
__device__ __forceinline__ void mma_tf32(float* c, const uint32_t* a,
                                         uint32_t b0, uint32_t b1) {
    asm volatile("mma.sync.aligned.m16n8k8.row.col.f32.tf32.tf32.f32 "
                 "{%0,%1,%2,%3}, {%4,%5,%6,%7}, {%8,%9}, {%0,%1,%2,%3};"
                 : "+f"(c[0]), "+f"(c[1]), "+f"(c[2]), "+f"(c[3])
                 : "r"(a[0]), "r"(a[1]), "r"(a[2]), "r"(a[3]), "r"(b0), "r"(b1));
}
__device__ __forceinline__ void cp_async16(uint32_t dst_smem, const void* src) {
    asm volatile("cp.async.cg.shared.global [%0], [%1], 16;"
                 :: "r"(dst_smem), "l"(src));
}
__device__ __forceinline__ void cp_commit() {
    asm volatile("cp.async.commit_group;");
}
__device__ __forceinline__ void cp_wait0() {
    asm volatile("cp.async.wait_group 0;");
}

// Scratch (static device globals; no runtime allocation)
__device__ float g_ht[(size_t)Bb * Dd * Tt];       // residual stream, TRANSPOSED [b][d][t]
__device__ uint32_t g_Wt[(size_t)Dd * Ee];         // W transposed, tf32 [d][e]
__device__ float g_bf[(size_t)Dd * Tt];            // bias[d] + freq[t][d], [d][t]
__device__ float g_Abar [Ll * DN];
__device__ float g_CB   [Ll * DN];                 // C * Bbar
__device__ float g_AbarP[Ll * DN];                 // Abar^TC
__device__ float g_swf0[Dd], g_swen[Dd];           // scale*weight per head
__device__ float g_hc[4];                          // SWf0, BWf0, SWen, BWen

// ---------------------------------------------------------------------------
// Mega-prep: ONE launch, partitioned by blockIdx. (X is consumed raw by the
// GEMM — fp32 bits are valid tf32 operands, HW truncates low mantissa bits.)
//   [0, 1024)      : g_bf[d][t] = bias[d] + freq[t][d]   (32x32 tiles)
//   [1024, 1280)   : g_Wt[d][e] = tf32(W[e][d])          (32x32 tiles)
//   [1280, 1408)   : SSM constants (256 elems/block)
//   [1408]         : head precompute
// ---------------------------------------------------------------------------
#define BFBLKS  ((Dd / 32) * (Tt / 32))       // 1024
#define WTBLKS  ((Dd / 32) * (Ee / 32))       // 256
#define SSMBLKS ((Ll * DN) / 256)             // 128
#define MPREP_BLOCKS (BFBLKS + WTBLKS + SSMBLKS + 1)   // 1409

__global__ __launch_bounds__(256)
void mega_prep_kernel(const float* __restrict__ W,
                      const float* __restrict__ bias, const float* __restrict__ freq,
                      const float* __restrict__ A_log, const float* __restrict__ B_ssm,
                      const float* __restrict__ C_ssm, const float* __restrict__ log_dt,
                      const float* __restrict__ s_f0, const float* __restrict__ bi_f0,
                      const float* __restrict__ w_f0,
                      const float* __restrict__ s_en, const float* __restrict__ bi_en,
                      const float* __restrict__ w_en) {
    __shared__ float sh[32][33];
    int bi = blockIdx.x;
    int tid = threadIdx.x;

    if (bi < BFBLKS) {
        int t2 = bi;
        int d0 = (t2 & 15) * 32, t0 = (t2 >> 4) * 32;
        int tx = tid & 31, ty = tid >> 5;       // (32, 8)
#pragma unroll
        for (int j = 0; j < 4; j++)
            sh[ty + j * 8][tx] = freq[(size_t)(t0 + ty + j * 8) * Dd + d0 + tx];
        __syncthreads();
#pragma unroll
        for (int j = 0; j < 4; j++)
            g_bf[(size_t)(d0 + ty + j * 8) * Tt + t0 + tx] =
                sh[tx][ty + j * 8] + bias[d0 + ty + j * 8];
    } else if (bi < BFBLKS + WTBLKS) {
        int t2 = bi - BFBLKS;
        int d0 = (t2 & 15) * 32, e0 = (t2 >> 4) * 32;
        int tx = tid & 31, ty = tid >> 5;
#pragma unroll
        for (int j = 0; j < 4; j++)
            sh[ty + j * 8][tx] = W[(size_t)(e0 + ty + j * 8) * Dd + d0 + tx];
        __syncthreads();
#pragma unroll
        for (int j = 0; j < 4; j++)
            g_Wt[(size_t)(d0 + ty + j * 8) * Ee + e0 + tx] = f2tf(sh[tx][ty + j * 8]);
    } else if (bi < BFBLKS + WTBLKS + SSMBLKS) {
        int idx = (bi - (BFBLKS + WTBLKS)) * 256 + tid;
        int l  = idx / DN;
        int dn = idx % DN;
        int d  = dn / Nn;
        float dt = expf(log_dt[l * Dd + d]);
        float A  = -expf(A_log[idx]);
        float dA = dt * A;
        float ab = expf(dA);
        g_Abar [idx] = ab;
        g_CB   [idx] = (ab - 1.0f) / A * B_ssm[idx] * C_ssm[idx];
        g_AbarP[idx] = expf(dA * (float)TC);
    } else {
        float* shf = &sh[0][0];
        float sum[4] = {0.0f, 0.0f, 0.0f, 0.0f};
#pragma unroll
        for (int k = 0; k < 2; k++) {
            int d = tid + k * 256;
            float wf = w_f0[d], we = w_en[d];
            float v0 = s_f0[d] * wf;
            float v1 = bi_f0[d] * wf;
            float v2 = s_en[d] * we;
            float v3 = bi_en[d] * we;
            g_swf0[d] = v0; g_swen[d] = v2;
            sum[0] += v0; sum[1] += v1; sum[2] += v2; sum[3] += v3;
        }
        int lane = tid & 31, w = tid >> 5;
#pragma unroll
        for (int j = 0; j < 4; j++) {
            float x = sum[j];
#pragma unroll
            for (int o = 16; o > 0; o >>= 1) x += __shfl_xor_sync(0xffffffffu, x, o);
            if (lane == 0) shf[j * 8 + w] = x;
        }
        __syncthreads();
        if (tid < 4) {
            float s = 0.0f;
#pragma unroll
            for (int k = 0; k < 8; k++) s += shf[tid * 8 + k];
            g_hc[tid] = s;
        }
    }
}

// ---------------------------------------------------------------------------
// TF32 GEMM, 128x128x16 tiles. A = raw X (fp32 bits as tf32 operands — HW
// truncation), B = pre-converted g_Wt. All smem fills via cp.async.
// ---------------------------------------------------------------------------
#define AST 20     // smem row stride (words)
#define BUFW 2560  // words per buffer (128 rows * 20)

__global__ __launch_bounds__(256, 2)
void gemm_tf32_kernel(const float* __restrict__ X) {
    __shared__ __align__(16) uint32_t smem[4 * BUFW];
    uint32_t* As = smem;
    uint32_t* Bs = smem + 2 * BUFW;

    int tid = threadIdx.x;
    int lane = tid & 31, wid = tid >> 5;
    int warp_m = wid >> 2, warp_n = wid & 3;
    int rowBase = blockIdx.y * 128;
    int colBase = blockIdx.x * 128;

    float acc[4][4][4];
#pragma unroll
    for (int i = 0; i < 4; i++)
#pragma unroll
        for (int j = 0; j < 4; j++)
#pragma unroll
            for (int k = 0; k < 4; k++) acc[i][j][k] = 0.0f;

    int a_row = (lane & 7) + ((lane >> 3) & 1) * 8;
    int a_colw = (lane >> 4) * 4;
    const uint32_t* aPtr = As + (warp_m * 64 + a_row) * AST + a_colw;
    int b_row = (lane & 7) + ((lane >> 4) << 3);
    int b_colw = ((lane >> 3) & 1) * 4;
    const uint32_t* bPtr = Bs + (warp_n * 32 + b_row) * AST + b_colw;

    int frow = tid >> 2;
    int fcol = (tid & 3) << 2;

    const float* Xp = X + (size_t)rowBase * Ee;
    const uint32_t* Wp = g_Wt + (size_t)colBase * Ee;

    uint32_t as0 = (uint32_t)__cvta_generic_to_shared(&As[frow * AST + fcol]);
    uint32_t as1 = (uint32_t)__cvta_generic_to_shared(&As[(frow + 64) * AST + fcol]);
    uint32_t bs0 = (uint32_t)__cvta_generic_to_shared(&Bs[frow * AST + fcol]);
    uint32_t bs1 = (uint32_t)__cvta_generic_to_shared(&Bs[(frow + 64) * AST + fcol]);

    cp_async16(as0, Xp + (size_t)frow * Ee + fcol);
    cp_async16(as1, Xp + (size_t)(frow + 64) * Ee + fcol);
    cp_async16(bs0, Wp + (size_t)frow * Ee + fcol);
    cp_async16(bs1, Wp + (size_t)(frow + 64) * Ee + fcol);
    cp_commit();
    cp_wait0();
    __syncthreads();

    int buf = 0;
    for (int kt = 16; kt < Ee; kt += 16) {
        int nb = buf ^ 1;
        uint32_t off = nb * (BUFW * 4);
        cp_async16(as0 + off, Xp + (size_t)frow * Ee + kt + fcol);
        cp_async16(as1 + off, Xp + (size_t)(frow + 64) * Ee + kt + fcol);
        cp_async16(bs0 + off, Wp + (size_t)frow * Ee + kt + fcol);
        cp_async16(bs1 + off, Wp + (size_t)(frow + 64) * Ee + kt + fcol);
        cp_commit();

        const uint32_t* aB = aPtr + buf * BUFW;
        const uint32_t* bB = bPtr + buf * BUFW;
        uint32_t a[2][4][4], bb[2][2][4];
#pragma unroll
        for (int k8 = 0; k8 < 2; k8++) {
#pragma unroll
            for (int mi = 0; mi < 4; mi++)
                ldsm4(a[k8][mi][0], a[k8][mi][1], a[k8][mi][2], a[k8][mi][3],
                      aB + mi * (16 * AST) + k8 * 8);
#pragma unroll
            for (int nj = 0; nj < 2; nj++)
                ldsm4(bb[k8][nj][0], bb[k8][nj][1], bb[k8][nj][2], bb[k8][nj][3],
                      bB + nj * (16 * AST) + k8 * 8);
        }
#pragma unroll
        for (int k8 = 0; k8 < 2; k8++)
#pragma unroll
            for (int mi = 0; mi < 4; mi++)
#pragma unroll
                for (int nj = 0; nj < 2; nj++) {
                    mma_tf32(acc[mi][2 * nj + 0], a[k8][mi], bb[k8][nj][0], bb[k8][nj][1]);
                    mma_tf32(acc[mi][2 * nj + 1], a[k8][mi], bb[k8][nj][2], bb[k8][nj][3]);
                }

        cp_wait0();
        __syncthreads();
        buf = nb;
    }

    {
        const uint32_t* aB = aPtr + buf * BUFW;
        const uint32_t* bB = bPtr + buf * BUFW;
        uint32_t a[2][4][4], bb[2][2][4];
#pragma unroll
        for (int k8 = 0; k8 < 2; k8++) {
#pragma unroll
            for (int mi = 0; mi < 4; mi++)
                ldsm4(a[k8][mi][0], a[k8][mi][1], a[k8][mi][2], a[k8][mi][3],
                      aB + mi * (16 * AST) + k8 * 8);
#pragma unroll
            for (int nj = 0; nj < 2; nj++)
                ldsm4(bb[k8][nj][0], bb[k8][nj][1], bb[k8][nj][2], bb[k8][nj][3],
                      bB + nj * (16 * AST) + k8 * 8);
        }
#pragma unroll
        for (int k8 = 0; k8 < 2; k8++)
#pragma unroll
            for (int mi = 0; mi < 4; mi++)
#pragma unroll
                for (int nj = 0; nj < 2; nj++) {
                    mma_tf32(acc[mi][2 * nj + 0], a[k8][mi], bb[k8][nj][0], bb[k8][nj][1]);
                    mma_tf32(acc[mi][2 * nj + 1], a[k8][mi], bb[k8][nj][2], bb[k8][nj][3]);
                }
    }
    __syncthreads();

    float* SE = (float*)smem;            // [64][132] floats
    int g = lane >> 2, tk = lane & 3;
    int b = rowBase >> 11;
    int t0 = rowBase & (Tt - 1);

#pragma unroll
    for (int p = 0; p < 2; p++) {
        if ((warp_n >> 1) == p) {
#pragma unroll
            for (int mi = 0; mi < 4; mi++) {
#pragma unroll
                for (int ni = 0; ni < 4; ni++) {
                    int rl = warp_m * 64 + mi * 16 + g;
                    int cl = warp_n * 32 + ni * 8 + 2 * tk;
                    int cls = cl - p * 64;
                    SE[cls * 132 + rl]           = acc[mi][ni][0];
                    SE[(cls + 1) * 132 + rl]     = acc[mi][ni][1];
                    SE[cls * 132 + rl + 8]       = acc[mi][ni][2];
                    SE[(cls + 1) * 132 + rl + 8] = acc[mi][ni][3];
                }
            }
        }
        __syncthreads();
#pragma unroll
        for (int i = 0; i < 8; i++) {
            int idx = i * 256 + tid;
            int dr = idx >> 5;
            int w  = idx & 31;
            int dg = colBase + p * 64 + dr;
            float4 v = *(float4*)&SE[dr * 132 + w * 4];
            float4 bf = *(const float4*)&g_bf[(size_t)dg * Tt + t0 + w * 4];
            v.x += bf.x; v.y += bf.y; v.z += bf.z; v.w += bf.w;
            *(float4*)&g_ht[((size_t)(b * Dd) + dg) * Tt + t0 + w * 4] = v;
        }
        __syncthreads();
    }
}

// ---------------------------------------------------------------------------
// Fused 4-layer S4 stack (R8 state — best measured, 59.6us). Block = 128 thr.
// ---------------------------------------------------------------------------
__global__ __launch_bounds__(128, 7)
void s4_stack_kernel(const float* __restrict__ D_skip) {
    __shared__ float sx[NCH * SXS];     // 8.7 KB
    __shared__ float us[DBLK * Tt];     // 16 KB

    int tid  = threadIdx.x;
    int dl   = tid & 1;
    int c    = tid >> 1;
    int b    = blockIdx.x >> 8;
    int dblk = blockIdx.x & 255;
    int d    = dblk * DBLK + dl;
    int rot  = tid & 31;
    int chanbase = dl * Tt + c * TC;

    int seg = tid & 3;
    int dn  = tid >> 2;
    int dl2 = dn >> 4, n2 = dn & 15;

    const float4* gb4 = (const float4*)(g_ht + ((size_t)(b * Dd) + dblk * DBLK) * Tt);
#pragma unroll
    for (int j = 0; j < 8; j++) {
        int p = j * 128 + tid;
        float4 v = gb4[p];
        int ch = p >> 9;
        int t  = (p & 511) << 2;
        int base = ch * Tt + (t & ~31);
        int rr = (((t >> 5) << 1) + ch) & 31;
        int i0 = t & 31;
        us[base + ((i0 + 0) ^ rr)] = v.x;
        us[base + ((i0 + 1) ^ rr)] = v.y;
        us[base + ((i0 + 2) ^ rr)] = v.z;
        us[base + ((i0 + 3) ^ rr)] = v.w;
    }
    __syncthreads();

#pragma unroll 1
    for (int l = 0; l < Ll; l++) {
        ull a2[8];
        {
            const float4* ap4 = (const float4*)(g_Abar + (size_t)l * DN + d * Nn);
#pragma unroll
            for (int q = 0; q < 4; q++) {
                float4 v = ap4[q];
                a2[2*q]   = pack2(v.x, v.y);
                a2[2*q+1] = pack2(v.z, v.w);
            }
        }

        ull z2[8];
#pragma unroll
        for (int q = 0; q < 8; q++) z2[q] = 0ull;
#pragma unroll
        for (int i = 0; i < TC; i++) {
            float uu = us[chanbase + (i ^ rot)];
            ull u2 = pack2(uu, uu);
#pragma unroll
            for (int q = 0; q < 8; q++)
                z2[q] = fma2(a2[q], z2[q], u2);
        }
        {
            ull* so = (ull*)(sx + c * SXS + dl * Nn);
#pragma unroll
            for (int q = 0; q < 8; q++) so[q] = z2[q];
        }
        __syncthreads();

        {
            float ap = g_AbarP[(size_t)l * DN + (dblk * DBLK + dl2) * Nn + n2];

            float F = 0.0f;
#pragma unroll
            for (int j = 0; j < 16; j++)
                F = fmaf(ap, F, sx[(seg * 16 + j) * SXS + dn]);

            float p2 = ap * ap, p4 = p2 * p2, p8 = p4 * p4;
            float m  = p8 * p8;

            float Fp = __shfl_up_sync(0xffffffffu, F, 1, 4);
            float mp = __shfl_up_sync(0xffffffffu, m, 1, 4);
            if (seg >= 1) { F = fmaf(m, Fp, F); m *= mp; }
            Fp = __shfl_up_sync(0xffffffffu, F, 2, 4);
            mp = __shfl_up_sync(0xffffffffu, m, 2, 4);
            if (seg >= 2) { F = fmaf(m, Fp, F); m *= mp; }

            float carry = __shfl_up_sync(0xffffffffu, F, 1, 4);
            if (seg == 0) carry = 0.0f;

            float xs = carry;
            float fcur = sx[(seg * 16) * SXS + dn];
#pragma unroll
            for (int j = 0; j < 16; j++) {
                float fnext = (j < 15) ? sx[(seg * 16 + j + 1) * SXS + dn] : 0.0f;
                sx[(seg * 16 + j) * SXS + dn] = xs;
                xs = fmaf(ap, xs, fcur);
                fcur = fnext;
            }
        }
        __syncthreads();

        ull cb2[8];
        {
            const float4* cp4 = (const float4*)(g_CB + (size_t)l * DN + d * Nn);
#pragma unroll
            for (int q = 0; q < 4; q++) {
                float4 v = cp4[q];
                cb2[2*q]   = pack2(v.x, v.y);
                cb2[2*q+1] = pack2(v.z, v.w);
            }
        }
        float dsk = D_skip[l * Dd + d];

        {
            const ull* si = (const ull*)(sx + c * SXS + dl * Nn);
#pragma unroll
            for (int q = 0; q < 8; q++) z2[q] = si[q];
        }

#pragma unroll
        for (int i = 0; i < TC; i++) {
            float uu = us[chanbase + (i ^ rot)];
            ull u2 = pack2(uu, uu);
            ull y2 = 0ull;
#pragma unroll
            for (int q = 0; q < 8; q++) {
                z2[q] = fma2(a2[q], z2[q], u2);
                y2 = fma2(z2[q], cb2[q], y2);
            }
            float ylo, yhi; unpack2(y2, ylo, yhi);
            float y = ylo + yhi;
            y = fmaf(dsk, uu, y);
            float yy = y * y;
            float inner2 = 1.5957691216057308f * (y + 0.044715f * y * yy);
            float e = __expf(-inner2);
            float g = __fdividef(y, 1.0f + e);
            us[chanbase + (i ^ rot)] = uu + g;
        }
    }
    __syncthreads();

    float4* gb4o = (float4*)(g_ht + ((size_t)(b * Dd) + dblk * DBLK) * Tt);
#pragma unroll
    for (int j = 0; j < 8; j++) {
        int p = j * 128 + tid;
        int ch = p >> 9;
        int t  = (p & 511) << 2;
        int base = ch * Tt + (t & ~31);
        int rr = (((t >> 5) << 1) + ch) & 31;
        int i0 = t & 31;
        float4 v;
        v.x = us[base + ((i0 + 0) ^ rr)];
        v.y = us[base + ((i0 + 1) ^ rr)];
        v.z = us[base + ((i0 + 2) ^ rr)];
        v.w = us[base + ((i0 + 3) ^ rr)];
        gb4o[p] = v;
    }
}

// ---------------------------------------------------------------------------
// Head (R15 state — best measured, 7.9us). float4-vectorized along t.
// Block = 512 thr: g = tid>>3 owns 8 d-rows; lt = tid&7 owns 4 t.
// ---------------------------------------------------------------------------
__global__ __launch_bounds__(512)
void head_kernel(const float* __restrict__ b_f0, const float* __restrict__ b_en,
                 float* __restrict__ out) {
    __shared__ float sh[16][4][32];
    int tid = threadIdx.x;
    int lane = tid & 31, w = tid >> 5;      // 16 warps
    int g = tid >> 3;                       // d-group 0..63 (8 d each)
    int lt = tid & 7;                       // t-lane (4 t each)
    int rowBase = blockIdx.x * 32;
    int b = rowBase >> 11, t0 = rowBase & (Tt - 1);

    const float* hp = g_ht + ((size_t)(b * Dd) + g * 8) * Tt + t0 + lt * 4;
    const float* swf = g_swf0 + g * 8;
    const float* swe = g_swen + g * 8;

    float acc[4][4];
#pragma unroll
    for (int j = 0; j < 4; j++)
#pragma unroll
        for (int k = 0; k < 4; k++) acc[j][k] = 0.0f;

#pragma unroll
    for (int dd = 0; dd < 8; dd++) {
        float4 v = *(const float4*)(hp + (size_t)dd * Tt);
        float wf = __ldg(swf + dd), we = __ldg(swe + dd);
        acc[0][0] += v.x; acc[0][1] += v.y; acc[0][2] += v.z; acc[0][3] += v.w;
        acc[1][0] = fmaf(v.x, v.x, acc[1][0]);
        acc[1][1] = fmaf(v.y, v.y, acc[1][1]);
        acc[1][2] = fmaf(v.z, v.z, acc[1][2]);
        acc[1][3] = fmaf(v.w, v.w, acc[1][3]);
        acc[2][0] = fmaf(v.x, wf, acc[2][0]);
        acc[2][1] = fmaf(v.y, wf, acc[2][1]);
        acc[2][2] = fmaf(v.z, wf, acc[2][2]);
        acc[2][3] = fmaf(v.w, wf, acc[2][3]);
        acc[3][0] = fmaf(v.x, we, acc[3][0]);
        acc[3][1] = fmaf(v.y, we, acc[3][1]);
        acc[3][2] = fmaf(v.z, we, acc[3][2]);
        acc[3][3] = fmaf(v.w, we, acc[3][3]);
    }

#pragma unroll
    for (int j = 0; j < 4; j++)
#pragma unroll
        for (int k = 0; k < 4; k++) {
            acc[j][k] += __shfl_xor_sync(0xffffffffu, acc[j][k], 8);
            acc[j][k] += __shfl_xor_sync(0xffffffffu, acc[j][k], 16);
        }

    if (lane < 8) {
#pragma unroll
        for (int j = 0; j < 4; j++)
#pragma unroll
            for (int k = 0; k < 4; k++)
                sh[w][j][lane * 4 + k] = acc[j][k];
    }
    __syncthreads();

    if (tid < 32) {
        int tt = tid;
        float a0 = 0.0f, a1 = 0.0f, a2 = 0.0f, a3 = 0.0f;
#pragma unroll
        for (int o = 0; o < 16; o++) {
            a0 += sh[o][0][tt]; a1 += sh[o][1][tt];
            a2 += sh[o][2][tt]; a3 += sh[o][3][tt];
        }
        float mu = a0 * (1.0f / Dd);
        float var = a1 * (1.0f / Dd) - mu * mu;
        float rstd = rsqrtf(var + 1e-5f);
        out[rowBase + tt]                   = rstd * (a2 - mu * g_hc[0]) + g_hc[1] + b_f0[0];
        out[(size_t)Bb * Tt + rowBase + tt] = rstd * (a3 - mu * g_hc[2]) + g_hc[3] + b_en[0];
    }
}

// ---------------------------------------------------------------------------
extern "C" void kernel_launch(void* const* d_in, const int* in_sizes, int n_in,
                              void* d_out, int out_size) {
    const float* text_emb = (const float*)d_in[0];
    const float* W_in     = (const float*)d_in[1];
    const float* b_in     = (const float*)d_in[2];
    const float* freq_pe  = (const float*)d_in[3];
    const float* A_log    = (const float*)d_in[4];
    const float* B_ssm    = (const float*)d_in[5];
    const float* C_ssm    = (const float*)d_in[6];
    const float* log_dt   = (const float*)d_in[7];
    const float* D_skip   = (const float*)d_in[8];
    const float* ln_f0_s  = (const float*)d_in[9];
    const float* ln_f0_b  = (const float*)d_in[10];
    const float* W_f0     = (const float*)d_in[11];
    const float* b_f0     = (const float*)d_in[12];
    const float* ln_en_s  = (const float*)d_in[13];
    const float* ln_en_b  = (const float*)d_in[14];
    const float* W_en     = (const float*)d_in[15];
    const float* b_en     = (const float*)d_in[16];
    float* out = (float*)d_out;

    mega_prep_kernel<<<MPREP_BLOCKS, 256>>>(
        W_in, b_in, freq_pe,
        A_log, B_ssm, C_ssm, log_dt,
        ln_f0_s, ln_f0_b, W_f0, ln_en_s, ln_en_b, W_en);

    dim3 ggrid(Dd / 128, (Bb * Tt) / 128);
    gemm_tf32_kernel<<<ggrid, 256>>>(text_emb);

    s4_stack_kernel<<<Bb * (Dd / DBLK), 128>>>(D_skip);

    head_kernel<<<(Bb * Tt) / 32, 512>>>(b_f0, b_en, out);
}